// round 13
// baseline (speedup 1.0000x reference)
#include <cuda_runtime.h>
#include <math.h>

#define Hh   128
#define Vv   50000
#define Bb   128
#define TC   50
#define TI   32
#define G3   384
#define EPIS 3

// ---------------- device scratch ----------------
__device__ float g_Etab[(size_t)Vv * G3];
__device__ float g_WtT_ig[128 * G3];
__device__ float g_WtT_qg[128 * G3];
__device__ float g_WtT_at[128 * G3];
__device__ float g_WtT_an[128 * G3];
__device__ float g_qemb[Bb * TI * Hh];
__device__ float g_QGI [Bb * TI * G3];
__device__ float g_encf[Bb * TC * Hh];
__device__ float g_q   [Bb * Hh];
__device__ float g_mem [Bb * Hh];
__device__ float g_Z   [Bb * TC * 512];
__device__ float g_Tanh[Bb * TC * Hh];
__device__ float g_G   [Bb * TC];
__device__ float g_GIat[Bb * TC * G3];
__device__ float g_ebuf[Bb * Hh];
__device__ float g_yq  [Bb * 256];
__device__ float g_GIan[Bb * G3];
__device__ float g_Hdec[16 * Bb * Hh];

__device__ __forceinline__ float sigmoidf(float x) { return 1.f / (1.f + expf(-x)); }

// Whh (384x128) -> k-major (128x384)
__global__ void transpose_kernel(const float* __restrict__ src, float* __restrict__ dst) {
    int idx = blockIdx.x * 256 + threadIdx.x;
    if (idx < G3 * 128) { int j = idx >> 7, k = idx & 127; dst[k * G3 + j] = src[idx]; }
}

// C[MxN] = act(A[MxK] @ B[NxK]^T + bias[N]); K % 32 == 0
__global__ __launch_bounds__(256)
void gemm_kernel(const float* __restrict__ A, const float* __restrict__ Bm,
                 const float* __restrict__ bias, float* __restrict__ C,
                 int M, int N, int K, int act)
{
    __shared__ float As[32][68];
    __shared__ float Bs[32][68];
    int tid = threadIdx.x;
    int tx = tid & 15, ty = tid >> 4;
    int bm = blockIdx.y * 64, bn = blockIdx.x * 64;
    float acc[4][4] = {};
    for (int k0 = 0; k0 < K; k0 += 32) {
#pragma unroll
        for (int r = 0; r < 2; r++) {
            int li = tid + r * 256;
            int lm = li >> 3;
            int lk = (li & 7) << 2;
            int gm = bm + lm; if (gm > M - 1) gm = M - 1;
            float4 va = *(const float4*)&A[(size_t)gm * K + k0 + lk];
            As[lk][lm] = va.x; As[lk+1][lm] = va.y; As[lk+2][lm] = va.z; As[lk+3][lm] = va.w;
            int gn = bn + lm; if (gn > N - 1) gn = N - 1;
            float4 vb = *(const float4*)&Bm[(size_t)gn * K + k0 + lk];
            Bs[lk][lm] = vb.x; Bs[lk+1][lm] = vb.y; Bs[lk+2][lm] = vb.z; Bs[lk+3][lm] = vb.w;
        }
        __syncthreads();
#pragma unroll
        for (int k = 0; k < 32; k++) {
            float4 a  = *(float4*)&As[k][ty << 2];
            float4 bv = *(float4*)&Bs[k][tx << 2];
            acc[0][0]+=a.x*bv.x; acc[0][1]+=a.x*bv.y; acc[0][2]+=a.x*bv.z; acc[0][3]+=a.x*bv.w;
            acc[1][0]+=a.y*bv.x; acc[1][1]+=a.y*bv.y; acc[1][2]+=a.y*bv.z; acc[1][3]+=a.y*bv.w;
            acc[2][0]+=a.z*bv.x; acc[2][1]+=a.z*bv.y; acc[2][2]+=a.z*bv.z; acc[2][3]+=a.z*bv.w;
            acc[3][0]+=a.w*bv.x; acc[3][1]+=a.w*bv.y; acc[3][2]+=a.w*bv.z; acc[3][3]+=a.w*bv.w;
        }
        __syncthreads();
    }
#pragma unroll
    for (int i = 0; i < 4; i++) {
        int m = bm + (ty << 2) + i;
        if (m < M) {
#pragma unroll
            for (int j = 0; j < 4; j++) {
                int n = bn + (tx << 2) + j;
                if (n < N) {
                    float v = acc[i][j] + bias[n];
                    if (act) v = tanhf(v);
                    C[(size_t)m * N + n] = v;
                }
            }
        }
    }
}

__global__ void qemb_kernel(const int* __restrict__ quest, const float* __restrict__ embed) {
    int idx = blockIdx.x * 256 + threadIdx.x;
    if (idx < Bb * TI * Hh) {
        int i = idx >> 7, h = idx & 127;
        g_qemb[idx] = embed[(size_t)quest[i] * Hh + h];
    }
}

__global__ void initmem_kernel() {
    int i = blockIdx.x * 256 + threadIdx.x;
    if (i < Bb * Hh) g_mem[i] = g_q[i];
}

__global__ void yq_kernel(const float* __restrict__ embed) {
    int idx = blockIdx.x * 256 + threadIdx.x;
    if (idx < Bb * 256) {
        int b = idx >> 8, c = idx & 255;
        g_yq[idx] = (c < 128) ? embed[2 * Hh + c] : g_q[b * Hh + (c - 128)];
    }
}

__global__ void zbuild_kernel() {
    int idx = blockIdx.x * 256 + threadIdx.x;
    if (idx >= Bb * TC * 512) return;
    int seq = idx >> 9, c = idx & 511;
    int part = c >> 7, h = c & 127;
    int b = seq / TC;
    float f = g_encf[seq * Hh + h];
    float v;
    if      (part == 0) v = f * g_q[b * Hh + h];
    else if (part == 1) v = f * g_mem[b * Hh + h];
    else if (part == 2) v = fabsf(f - g_q[b * Hh + h]);
    else                v = fabsf(f - g_mem[b * Hh + h]);
    g_Z[idx] = v;
}

__global__ void gatered_kernel(const float* __restrict__ W2, const float* __restrict__ b2p) {
    int warp = threadIdx.x >> 5, lane = threadIdx.x & 31;
    int row = blockIdx.x * 8 + warp;
    if (row >= Bb * TC) return;
    float s = 0.f;
    for (int k = lane; k < Hh; k += 32) s += g_Tanh[row * Hh + k] * W2[k];
#pragma unroll
    for (int o = 16; o; o >>= 1) s += __shfl_xor_sync(0xffffffff, s, o);
    if (lane == 0) g_G[row] = sigmoidf(s + b2p[0]);
}

// memory = gru_cell(ebuf, memory, me_*)  -- one block per batch row, 384 threads
__global__ void memstep_kernel(const float* __restrict__ Wih, const float* __restrict__ Whh,
                               const float* __restrict__ bih, const float* __restrict__ bhh)
{
    __shared__ float xs[128], hs[128], gis[384], ghs[384];
    int b = blockIdx.x, tid = threadIdx.x;
    if (tid < 128) { xs[tid] = g_ebuf[b * Hh + tid]; hs[tid] = g_mem[b * Hh + tid]; }
    __syncthreads();
    float ai = bih[tid], ah = bhh[tid];
    for (int k = 0; k < 128; k++) ai += xs[k] * __ldg(&Wih[tid * 128 + k]);
    for (int k = 0; k < 128; k++) ah += hs[k] * __ldg(&Whh[tid * 128 + k]);
    gis[tid] = ai; ghs[tid] = ah;
    __syncthreads();
    if (tid < 128) {
        float r = sigmoidf(gis[tid] + ghs[tid]);
        float z = sigmoidf(gis[128 + tid] + ghs[128 + tid]);
        float n = tanhf(gis[256 + tid] + r * ghs[256 + tid]);
        g_mem[b * Hh + tid] = (1.f - z) * n + z * hs[tid];
    }
}

// -------- fused fact + question GRU recurrence: 32 seqs/block, 512 threads --------
// thread owns (h_, 8-seq tile), computes all 3 gates itself.
__global__ __launch_bounds__(512, 1)
void recur_kernel(const int* __restrict__ facts, const int* __restrict__ fmasks,
                  const int* __restrict__ qmasks,
                  const float* __restrict__ igbhh, const float* __restrict__ qgbhh,
                  int factBlocks)
{
    extern __shared__ float sm[];
    float* Wsm = sm;                   // 49152
    float* hsm = sm + 49152;           // 32*132
    float* bsm = hsm + 32 * 132;       // 384
    int*   flen = (int*)(bsm + 384);   // 32

    bool isQ = (blockIdx.x >= factBlocks);
    int  seq0 = (isQ ? (blockIdx.x - factBlocks) : blockIdx.x) * 32;
    const float* WT   = isQ ? g_WtT_qg : g_WtT_ig;
    const float* bhh  = isQ ? qgbhh : igbhh;
    const int*  masks = isQ ? qmasks : fmasks;
    float*      outp  = isQ ? g_q : g_encf;

    int tid = threadIdx.x;
    for (int i = tid * 4; i < 128 * G3; i += 2048)
        *(float4*)&Wsm[i] = *(const float4*)&WT[i];
    if (tid < 384) bsm[tid] = bhh[tid];
    if (tid < 32) {
        int c = 0;
        for (int t = 0; t < TI; t++) c += (masks[(seq0 + tid) * TI + t] == 0) ? 1 : 0;
        flen[tid] = (c > 0) ? c : 1;
    }
    for (int i = tid; i < 32 * 132; i += 512) hsm[i] = 0.f;
    __syncthreads();

    int h_ = tid & 127;
    int sbase = (tid >> 7) * 8;
    float br = bsm[h_], bz = bsm[128 + h_], bn_ = bsm[256 + h_];

    for (int t = 0; t < TI; t++) {
        float gr[8], gz[8], gn[8];
#pragma unroll
        for (int si = 0; si < 8; si++) {
            int gs = seq0 + sbase + si;
            const float* gi = isQ ? (g_QGI + ((size_t)gs * TI + t) * G3)
                                  : (g_Etab + (size_t)__ldg(&facts[gs * TI + t]) * G3);
            gr[si] = __ldg(&gi[h_]);
            gz[si] = __ldg(&gi[128 + h_]);
            gn[si] = __ldg(&gi[256 + h_]);
        }
        float ar[8] = {}, az[8] = {}, aw[8] = {};
#pragma unroll 2
        for (int k0 = 0; k0 < 128; k0 += 4) {
            float wr0 = Wsm[(k0+0)*G3 + h_],       wr1 = Wsm[(k0+1)*G3 + h_];
            float wr2 = Wsm[(k0+2)*G3 + h_],       wr3 = Wsm[(k0+3)*G3 + h_];
            float wz0 = Wsm[(k0+0)*G3 + 128 + h_], wz1 = Wsm[(k0+1)*G3 + 128 + h_];
            float wz2 = Wsm[(k0+2)*G3 + 128 + h_], wz3 = Wsm[(k0+3)*G3 + 128 + h_];
            float wn0 = Wsm[(k0+0)*G3 + 256 + h_], wn1 = Wsm[(k0+1)*G3 + 256 + h_];
            float wn2 = Wsm[(k0+2)*G3 + 256 + h_], wn3 = Wsm[(k0+3)*G3 + 256 + h_];
#pragma unroll
            for (int si = 0; si < 8; si++) {
                float4 h4 = *(float4*)&hsm[(sbase + si) * 132 + k0];
                ar[si] += wr0*h4.x + wr1*h4.y + wr2*h4.z + wr3*h4.w;
                az[si] += wz0*h4.x + wz1*h4.y + wz2*h4.z + wz3*h4.w;
                aw[si] += wn0*h4.x + wn1*h4.y + wn2*h4.z + wn3*h4.w;
            }
        }
        float hn[8];
#pragma unroll
        for (int si = 0; si < 8; si++) {
            float ho = hsm[(sbase + si) * 132 + h_];
            float r = sigmoidf(gr[si] + ar[si] + br);
            float z = sigmoidf(gz[si] + az[si] + bz);
            float n = tanhf(gn[si] + r * (aw[si] + bn_));
            hn[si] = (1.f - z) * n + z * ho;
        }
        __syncthreads();
#pragma unroll
        for (int si = 0; si < 8; si++) {
            int s = sbase + si;
            hsm[s * 132 + h_] = hn[si];
            if (t == flen[s] - 1) outp[(size_t)(seq0 + s) * Hh + h_] = hn[si];
        }
        __syncthreads();
    }
}

// -------- episode attention scan: one block per batch row --------
__global__ __launch_bounds__(384, 1)
void scan_kernel(const float* __restrict__ at_bhh)
{
    extern __shared__ float sm[];
    float* Wsm = sm;              // 49152
    float* ghs = sm + 49152;      // 384
    float* hv  = ghs + 384;       // 128
    float* bs  = hv + 128;        // 384
    int b = blockIdx.x, tid = threadIdx.x;
    for (int i = tid * 4; i < 128 * G3; i += 1536)
        *(float4*)&Wsm[i] = *(const float4*)&g_WtT_at[i];
    bs[tid] = at_bhh[tid];
    if (tid < 128) hv[tid] = 0.f;
    __syncthreads();
    for (int t = 0; t < TC; t++) {
        float a0 = 0.f, a1 = 0.f;
#pragma unroll 8
        for (int k0 = 0; k0 < 128; k0 += 4) {
            float4 h4 = *(float4*)&hv[k0];
            a0 += h4.x * Wsm[(k0+0)*G3 + tid];
            a1 += h4.y * Wsm[(k0+1)*G3 + tid];
            a0 += h4.z * Wsm[(k0+2)*G3 + tid];
            a1 += h4.w * Wsm[(k0+3)*G3 + tid];
        }
        ghs[tid] = a0 + a1 + bs[tid];
        __syncthreads();
        if (tid < 128) {
            int seq = b * TC + t;
            const float* gi = g_GIat + (size_t)seq * G3;
            float r = sigmoidf(gi[tid] + ghs[tid]);
            float z = sigmoidf(gi[128 + tid] + ghs[128 + tid]);
            float n = tanhf(gi[256 + tid] + r * ghs[256 + tid]);
            float ho = hv[tid];
            float h2 = (1.f - z) * n + z * ho;
            float g = g_G[seq];
            hv[tid] = g * h2 + (1.f - g) * ho;
        }
        __syncthreads();
    }
    if (tid < 128) g_ebuf[b * Hh + tid] = hv[tid];
}

// -------- answer decode: one block per batch row --------
__global__ __launch_bounds__(384, 1)
void decode_kernel(const float* __restrict__ an_bhh, int nd)
{
    extern __shared__ float sm[];
    float* Wsm = sm;
    float* ghs = sm + 49152;
    float* hv  = ghs + 384;
    float* bs  = hv + 128;
    int b = blockIdx.x, tid = threadIdx.x;
    for (int i = tid * 4; i < 128 * G3; i += 1536)
        *(float4*)&Wsm[i] = *(const float4*)&g_WtT_an[i];
    bs[tid] = an_bhh[tid];
    if (tid < 128) hv[tid] = g_mem[b * Hh + tid];
    __syncthreads();
    const float* gi = g_GIan + b * G3;   // constant across steps
    for (int t = 0; t < nd; t++) {
        float a0 = 0.f, a1 = 0.f;
#pragma unroll 8
        for (int k0 = 0; k0 < 128; k0 += 4) {
            float4 h4 = *(float4*)&hv[k0];
            a0 += h4.x * Wsm[(k0+0)*G3 + tid];
            a1 += h4.y * Wsm[(k0+1)*G3 + tid];
            a0 += h4.z * Wsm[(k0+2)*G3 + tid];
            a1 += h4.w * Wsm[(k0+3)*G3 + tid];
        }
        ghs[tid] = a0 + a1 + bs[tid];
        __syncthreads();
        if (tid < 128) {
            float r = sigmoidf(gi[tid] + ghs[tid]);
            float z = sigmoidf(gi[128 + tid] + ghs[128 + tid]);
            float n = tanhf(gi[256 + tid] + r * ghs[256 + tid]);
            float h2 = (1.f - z) * n + z * hv[tid];
            hv[tid] = h2;
            g_Hdec[((size_t)b * nd + t) * Hh + tid] = h2;
        }
        __syncthreads();
    }
}

// -------- per-row log-softmax, row staged in smem --------
__global__ __launch_bounds__(256, 1)
void lsm_kernel(float* __restrict__ out)
{
    extern __shared__ float row[];       // Vv floats
    __shared__ float red[256];
    size_t base = (size_t)blockIdx.x * Vv;
    int tid = threadIdx.x;
    float mx = -1e30f;
    for (int i = tid * 4; i < Vv; i += 1024) {
        float4 v = *(float4*)&out[base + i];
        *(float4*)&row[i] = v;
        mx = fmaxf(mx, fmaxf(fmaxf(v.x, v.y), fmaxf(v.z, v.w)));
    }
    red[tid] = mx; __syncthreads();
    for (int o = 128; o; o >>= 1) { if (tid < o) red[tid] = fmaxf(red[tid], red[tid + o]); __syncthreads(); }
    mx = red[0];
    __syncthreads();
    float s = 0.f;
    for (int i = tid; i < Vv; i += 256) s += expf(row[i] - mx);
    red[tid] = s; __syncthreads();
    for (int o = 128; o; o >>= 1) { if (tid < o) red[tid] += red[tid + o]; __syncthreads(); }
    float lse = mx + logf(red[0]);
    for (int i = tid * 4; i < Vv; i += 1024) {
        float4 v = *(float4*)&row[i];
        v.x -= lse; v.y -= lse; v.z -= lse; v.w -= lse;
        *(float4*)&out[base + i] = v;
    }
}

// ---------------- host ----------------
static void* symaddr(const void* s) { void* p = nullptr; cudaGetSymbolAddress(&p, s); return p; }

extern "C" void kernel_launch(void* const* d_in, const int* in_sizes, int n_in,
                              void* d_out, int out_size)
{
    const int*   facts  = (const int*)d_in[0];
    const int*   fmask  = (const int*)d_in[1];
    const int*   quest  = (const int*)d_in[2];
    const int*   qmask  = (const int*)d_in[3];
    const float* embed  = (const float*)d_in[5];
    const float* ig_Wih = (const float*)d_in[6],  *ig_Whh = (const float*)d_in[7];
    const float* ig_bih = (const float*)d_in[8],  *ig_bhh = (const float*)d_in[9];
    const float* qg_Wih = (const float*)d_in[10], *qg_Whh = (const float*)d_in[11];
    const float* qg_bih = (const float*)d_in[12], *qg_bhh = (const float*)d_in[13];
    const float* at_Wih = (const float*)d_in[14], *at_Whh = (const float*)d_in[15];
    const float* at_bih = (const float*)d_in[16], *at_bhh = (const float*)d_in[17];
    const float* me_Wih = (const float*)d_in[18], *me_Whh = (const float*)d_in[19];
    const float* me_bih = (const float*)d_in[20], *me_bhh = (const float*)d_in[21];
    const float* an_Wih = (const float*)d_in[22], *an_Whh = (const float*)d_in[23];
    const float* an_bih = (const float*)d_in[24], *an_bhh = (const float*)d_in[25];
    const float* gate_W1 = (const float*)d_in[26], *gate_b1 = (const float*)d_in[27];
    const float* gate_W2 = (const float*)d_in[28], *gate_b2 = (const float*)d_in[29];
    const float* fc_W   = (const float*)d_in[30], *fc_b   = (const float*)d_in[31];
    float* out = (float*)d_out;
    (void)fmask; (void)in_sizes; (void)n_in;

    int nd = out_size / (Bb * Vv);
    if (nd < 1) nd = 1; if (nd > 16) nd = 16;

    float* Etab  = (float*)symaddr(g_Etab);
    float* WtTig = (float*)symaddr(g_WtT_ig);
    float* WtTqg = (float*)symaddr(g_WtT_qg);
    float* WtTat = (float*)symaddr(g_WtT_at);
    float* WtTan = (float*)symaddr(g_WtT_an);
    float* qemb  = (float*)symaddr(g_qemb);
    float* QGI   = (float*)symaddr(g_QGI);
    float* encf  = (float*)symaddr(g_encf);
    float* Z     = (float*)symaddr(g_Z);
    float* Tanhb = (float*)symaddr(g_Tanh);
    float* GIat  = (float*)symaddr(g_GIat);
    float* yqb   = (float*)symaddr(g_yq);
    float* GIan  = (float*)symaddr(g_GIan);
    float* Hdec  = (float*)symaddr(g_Hdec);

    const int RECUR_SMEM = (49152 + 32 * 132 + 384) * 4 + 32 * 4;  // 215168
    const int SCAN_SMEM  = (49152 + 384 + 128 + 384) * 4;          // 200192
    const int LSM_SMEM   = Vv * 4;                                 // 200000
    cudaFuncSetAttribute(recur_kernel,  cudaFuncAttributeMaxDynamicSharedMemorySize, RECUR_SMEM);
    cudaFuncSetAttribute(scan_kernel,   cudaFuncAttributeMaxDynamicSharedMemorySize, SCAN_SMEM);
    cudaFuncSetAttribute(decode_kernel, cudaFuncAttributeMaxDynamicSharedMemorySize, SCAN_SMEM);
    cudaFuncSetAttribute(lsm_kernel,    cudaFuncAttributeMaxDynamicSharedMemorySize, LSM_SMEM);

    // 1. pre-transpose recurrent weights to k-major
    transpose_kernel<<<192, 256>>>(ig_Whh, WtTig);
    transpose_kernel<<<192, 256>>>(qg_Whh, WtTqg);
    transpose_kernel<<<192, 256>>>(at_Whh, WtTat);
    transpose_kernel<<<192, 256>>>(an_Whh, WtTan);

    // 2. Etab = embed @ ig_Wih^T + ig_bih  (vocab-level input projection)
    { dim3 g(6, (Vv + 63) / 64); gemm_kernel<<<g, 256>>>(embed, ig_Wih, ig_bih, Etab, Vv, G3, Hh, 0); }

    // 3. question input projections
    qemb_kernel<<<(Bb * TI * Hh + 255) / 256, 256>>>(quest, embed);
    { dim3 g(6, (Bb * TI + 63) / 64); gemm_kernel<<<g, 256>>>(qemb, qg_Wih, qg_bih, QGI, Bb * TI, G3, Hh, 0); }

    // 4. fused fact + question recurrence
    const int FACT_BLOCKS = (Bb * TC) / 32;    // 200
    recur_kernel<<<FACT_BLOCKS + Bb / 32, 512, RECUR_SMEM>>>(
        facts, fmask, qmask, ig_bhh, qg_bhh, FACT_BLOCKS);

    // 5. episodes
    initmem_kernel<<<(Bb * Hh + 255) / 256, 256>>>();
    { dim3 g(6, (Bb * TC + 63) / 64); gemm_kernel<<<g, 256>>>(encf, at_Wih, at_bih, GIat, Bb * TC, G3, Hh, 0); }
    for (int ep = 0; ep < EPIS; ep++) {
        zbuild_kernel<<<(Bb * TC * 512 + 255) / 256, 256>>>();
        { dim3 g(2, (Bb * TC + 63) / 64); gemm_kernel<<<g, 256>>>(Z, gate_W1, gate_b1, Tanhb, Bb * TC, Hh, 512, 1); }
        gatered_kernel<<<(Bb * TC + 7) / 8, 256>>>(gate_W2, gate_b2);
        scan_kernel<<<Bb, 384, SCAN_SMEM>>>(at_bhh);
        memstep_kernel<<<Bb, 384>>>(me_Wih, me_Whh, me_bih, me_bhh);
    }

    // 6. decode
    yq_kernel<<<(Bb * 256 + 255) / 256, 256>>>(embed);
    { dim3 g(6, 2); gemm_kernel<<<g, 256>>>(yqb, an_Wih, an_bih, GIan, Bb, G3, 256, 0); }
    decode_kernel<<<Bb, 384, SCAN_SMEM>>>(an_bhh, nd);

    // 7. logits GEMM straight into d_out, then in-place log-softmax
    { dim3 g((Vv + 63) / 64, (Bb * nd + 63) / 64);
      gemm_kernel<<<g, 256>>>(Hdec, fc_W, fc_b, out, Bb * nd, Vv, Hh, 0); }
    lsm_kernel<<<Bb * nd, 256, LSM_SMEM>>>(out);
}

// round 14
// speedup vs baseline: 1.2891x; 1.2891x over previous
#include <cuda_runtime.h>
#include <math.h>

#define Hh   128
#define Vv   50000
#define Bb   128
#define TC   50
#define TI   32
#define G3   384
#define EPIS 3
#define SPB  48     // seqs per recur block
#define SPT  12     // seqs per thread (4 groups of 128 threads)

// ---------------- device scratch ----------------
__device__ float g_Etab[(size_t)Vv * G3];
__device__ float g_WtT_ig[128 * G3];
__device__ float g_WtT_qg[128 * G3];
__device__ float g_WtT_at[128 * G3];
__device__ float g_WtT_an[128 * G3];
__device__ float g_WtT_meWih[128 * G3];
__device__ float g_WtT_meWhh[128 * G3];
__device__ float g_qemb[Bb * TI * Hh];
__device__ float g_QGI [Bb * TI * G3];
__device__ float g_encf[Bb * TC * Hh];
__device__ float g_q   [Bb * Hh];
__device__ float g_mem [Bb * Hh];
__device__ float g_Z   [Bb * TC * 512];
__device__ float g_Tanh[Bb * TC * Hh];
__device__ float g_G   [Bb * TC];
__device__ float g_GIat[Bb * TC * G3];
__device__ float g_ebuf[Bb * Hh];
__device__ float g_yq  [Bb * 256];
__device__ float g_GIan[Bb * G3];
__device__ float g_Hdec[16 * Bb * Hh];

__device__ __forceinline__ float sigmoidf(float x) { return 1.f / (1.f + expf(-x)); }

// six Whh-style (384x128) -> k-major (128x384) transposes in one launch
__global__ void transpose6_kernel(const float* __restrict__ s0, const float* __restrict__ s1,
                                  const float* __restrict__ s2, const float* __restrict__ s3,
                                  const float* __restrict__ s4, const float* __restrict__ s5,
                                  float* __restrict__ d0, float* __restrict__ d1,
                                  float* __restrict__ d2, float* __restrict__ d3,
                                  float* __restrict__ d4, float* __restrict__ d5)
{
    int region = blockIdx.x / 192;
    int idx = (blockIdx.x % 192) * 256 + threadIdx.x;
    if (idx >= G3 * 128) return;
    const float* src; float* dst;
    switch (region) {
        case 0: src = s0; dst = d0; break;
        case 1: src = s1; dst = d1; break;
        case 2: src = s2; dst = d2; break;
        case 3: src = s3; dst = d3; break;
        case 4: src = s4; dst = d4; break;
        default: src = s5; dst = d5; break;
    }
    int j = idx >> 7, k = idx & 127;
    dst[k * G3 + j] = src[idx];
}

// C[MxN] = act(A[MxK] @ B[NxK]^T + bias[N]); K % 32 == 0
__global__ __launch_bounds__(256)
void gemm_kernel(const float* __restrict__ A, const float* __restrict__ Bm,
                 const float* __restrict__ bias, float* __restrict__ C,
                 int M, int N, int K, int act)
{
    __shared__ float As[32][68];
    __shared__ float Bs[32][68];
    int tid = threadIdx.x;
    int tx = tid & 15, ty = tid >> 4;
    int bm = blockIdx.y * 64, bn = blockIdx.x * 64;
    float acc[4][4] = {};
    for (int k0 = 0; k0 < K; k0 += 32) {
#pragma unroll
        for (int r = 0; r < 2; r++) {
            int li = tid + r * 256;
            int lm = li >> 3;
            int lk = (li & 7) << 2;
            int gm = bm + lm; if (gm > M - 1) gm = M - 1;
            float4 va = *(const float4*)&A[(size_t)gm * K + k0 + lk];
            As[lk][lm] = va.x; As[lk+1][lm] = va.y; As[lk+2][lm] = va.z; As[lk+3][lm] = va.w;
            int gn = bn + lm; if (gn > N - 1) gn = N - 1;
            float4 vb = *(const float4*)&Bm[(size_t)gn * K + k0 + lk];
            Bs[lk][lm] = vb.x; Bs[lk+1][lm] = vb.y; Bs[lk+2][lm] = vb.z; Bs[lk+3][lm] = vb.w;
        }
        __syncthreads();
#pragma unroll
        for (int k = 0; k < 32; k++) {
            float4 a  = *(float4*)&As[k][ty << 2];
            float4 bv = *(float4*)&Bs[k][tx << 2];
            acc[0][0]+=a.x*bv.x; acc[0][1]+=a.x*bv.y; acc[0][2]+=a.x*bv.z; acc[0][3]+=a.x*bv.w;
            acc[1][0]+=a.y*bv.x; acc[1][1]+=a.y*bv.y; acc[1][2]+=a.y*bv.z; acc[1][3]+=a.y*bv.w;
            acc[2][0]+=a.z*bv.x; acc[2][1]+=a.z*bv.y; acc[2][2]+=a.z*bv.z; acc[2][3]+=a.z*bv.w;
            acc[3][0]+=a.w*bv.x; acc[3][1]+=a.w*bv.y; acc[3][2]+=a.w*bv.z; acc[3][3]+=a.w*bv.w;
        }
        __syncthreads();
    }
#pragma unroll
    for (int i = 0; i < 4; i++) {
        int m = bm + (ty << 2) + i;
        if (m < M) {
#pragma unroll
            for (int j = 0; j < 4; j++) {
                int n = bn + (tx << 2) + j;
                if (n < N) {
                    float v = acc[i][j] + bias[n];
                    if (act) v = tanhf(v);
                    C[(size_t)m * N + n] = v;
                }
            }
        }
    }
}

__global__ void qemb_kernel(const int* __restrict__ quest, const float* __restrict__ embed) {
    int idx = blockIdx.x * 256 + threadIdx.x;
    if (idx < Bb * TI * Hh) {
        int i = idx >> 7, h = idx & 127;
        g_qemb[idx] = embed[(size_t)quest[i] * Hh + h];
    }
}

__global__ void initmem_kernel() {
    int i = blockIdx.x * 256 + threadIdx.x;
    if (i < Bb * Hh) g_mem[i] = g_q[i];
}

__global__ void yq_kernel(const float* __restrict__ embed) {
    int idx = blockIdx.x * 256 + threadIdx.x;
    if (idx < Bb * 256) {
        int b = idx >> 8, c = idx & 255;
        g_yq[idx] = (c < 128) ? embed[2 * Hh + c] : g_q[b * Hh + (c - 128)];
    }
}

__global__ void zbuild_kernel() {
    int idx = blockIdx.x * 256 + threadIdx.x;
    if (idx >= Bb * TC * 512) return;
    int seq = idx >> 9, c = idx & 511;
    int part = c >> 7, h = c & 127;
    int b = seq / TC;
    float f = g_encf[seq * Hh + h];
    float v;
    if      (part == 0) v = f * g_q[b * Hh + h];
    else if (part == 1) v = f * g_mem[b * Hh + h];
    else if (part == 2) v = fabsf(f - g_q[b * Hh + h]);
    else                v = fabsf(f - g_mem[b * Hh + h]);
    g_Z[idx] = v;
}

__global__ void gatered_kernel(const float* __restrict__ W2, const float* __restrict__ b2p) {
    int warp = threadIdx.x >> 5, lane = threadIdx.x & 31;
    int row = blockIdx.x * 8 + warp;
    if (row >= Bb * TC) return;
    float s = 0.f;
    for (int k = lane; k < Hh; k += 32) s += g_Tanh[row * Hh + k] * W2[k];
#pragma unroll
    for (int o = 16; o; o >>= 1) s += __shfl_xor_sync(0xffffffff, s, o);
    if (lane == 0) g_G[row] = sigmoidf(s + b2p[0]);
}

// memory = gru_cell(ebuf, memory, me_*) -- one block per batch row, 384 threads
// weights pre-transposed to k-major -> coalesced loads
__global__ void memstep_kernel(const float* __restrict__ bih, const float* __restrict__ bhh)
{
    __shared__ float xs[128], hs[128], gis[384], ghs[384];
    int b = blockIdx.x, tid = threadIdx.x;
    if (tid < 128) { xs[tid] = g_ebuf[b * Hh + tid]; hs[tid] = g_mem[b * Hh + tid]; }
    __syncthreads();
    float ai = bih[tid], ah = bhh[tid];
#pragma unroll 8
    for (int k = 0; k < 128; k++) {
        ai += xs[k] * __ldg(&g_WtT_meWih[k * G3 + tid]);
        ah += hs[k] * __ldg(&g_WtT_meWhh[k * G3 + tid]);
    }
    gis[tid] = ai; ghs[tid] = ah;
    __syncthreads();
    if (tid < 128) {
        float r = sigmoidf(gis[tid] + ghs[tid]);
        float z = sigmoidf(gis[128 + tid] + ghs[128 + tid]);
        float n = tanhf(gis[256 + tid] + r * ghs[256 + tid]);
        g_mem[b * Hh + tid] = (1.f - z) * n + z * hs[tid];
    }
}

// -------- fused fact + question GRU recurrence: 48 seqs/block, 512 threads --------
// 4 independent 128-thread groups x 12 seqs each; per-group named barriers.
__global__ __launch_bounds__(512, 1)
void recur_kernel(const int* __restrict__ facts, const int* __restrict__ fmasks,
                  const int* __restrict__ qmasks,
                  const float* __restrict__ igbhh, const float* __restrict__ qgbhh,
                  int factBlocks)
{
    extern __shared__ float sm[];
    float* Wsm = sm;                   // 49152 floats
    float* hsm = sm + 49152;           // SPB*132
    float* bsm = hsm + SPB * 132;      // 384
    int*   flen = (int*)(bsm + 384);   // SPB

    bool isQ = (blockIdx.x >= factBlocks);
    int  seq0 = (isQ ? (blockIdx.x - factBlocks) : blockIdx.x) * SPB;
    int  nTot = isQ ? Bb : Bb * TC;
    const float* WT   = isQ ? g_WtT_qg : g_WtT_ig;
    const float* bhh  = isQ ? qgbhh : igbhh;
    const int*  masks = isQ ? qmasks : fmasks;
    float*      outp  = isQ ? g_q : g_encf;

    int tid = threadIdx.x;
    for (int i = tid * 4; i < 128 * G3; i += 2048)
        *(float4*)&Wsm[i] = *(const float4*)&WT[i];
    if (tid < 384) bsm[tid] = bhh[tid];
    if (tid < SPB) {
        int gs = seq0 + tid; if (gs > nTot - 1) gs = nTot - 1;
        int c = 0;
        for (int t = 0; t < TI; t++) c += (masks[gs * TI + t] == 0) ? 1 : 0;
        flen[tid] = (c > 0) ? c : 1;
    }
    for (int i = tid; i < SPB * 132; i += 512) hsm[i] = 0.f;
    __syncthreads();

    int h_ = tid & 127;
    int grp = tid >> 7;                 // 0..3
    int sbase = grp * SPT;
    int barid = grp + 1;
    float br = bsm[h_], bz = bsm[128 + h_], bn_ = bsm[256 + h_];

    for (int t = 0; t < TI; t++) {
        float gr[SPT], gz[SPT], gn[SPT];
#pragma unroll
        for (int si = 0; si < SPT; si++) {
            int gs = seq0 + sbase + si; if (gs > nTot - 1) gs = nTot - 1;
            const float* gi = isQ ? (g_QGI + ((size_t)gs * TI + t) * G3)
                                  : (g_Etab + (size_t)__ldg(&facts[gs * TI + t]) * G3);
            gr[si] = __ldg(&gi[h_]);
            gz[si] = __ldg(&gi[128 + h_]);
            gn[si] = __ldg(&gi[256 + h_]);
        }
        float ar[SPT] = {}, az[SPT] = {}, aw[SPT] = {};
#pragma unroll 2
        for (int k0 = 0; k0 < 128; k0 += 4) {
            float wr0 = Wsm[(k0+0)*G3 + h_],       wr1 = Wsm[(k0+1)*G3 + h_];
            float wr2 = Wsm[(k0+2)*G3 + h_],       wr3 = Wsm[(k0+3)*G3 + h_];
            float wz0 = Wsm[(k0+0)*G3 + 128 + h_], wz1 = Wsm[(k0+1)*G3 + 128 + h_];
            float wz2 = Wsm[(k0+2)*G3 + 128 + h_], wz3 = Wsm[(k0+3)*G3 + 128 + h_];
            float wn0 = Wsm[(k0+0)*G3 + 256 + h_], wn1 = Wsm[(k0+1)*G3 + 256 + h_];
            float wn2 = Wsm[(k0+2)*G3 + 256 + h_], wn3 = Wsm[(k0+3)*G3 + 256 + h_];
#pragma unroll
            for (int si = 0; si < SPT; si++) {
                float4 h4 = *(float4*)&hsm[(sbase + si) * 132 + k0];
                ar[si] += wr0*h4.x + wr1*h4.y + wr2*h4.z + wr3*h4.w;
                az[si] += wz0*h4.x + wz1*h4.y + wz2*h4.z + wz3*h4.w;
                aw[si] += wn0*h4.x + wn1*h4.y + wn2*h4.z + wn3*h4.w;
            }
        }
        float hn[SPT];
#pragma unroll
        for (int si = 0; si < SPT; si++) {
            float ho = hsm[(sbase + si) * 132 + h_];
            float r = sigmoidf(gr[si] + ar[si] + br);
            float z = sigmoidf(gz[si] + az[si] + bz);
            float n = tanhf(gn[si] + r * (aw[si] + bn_));
            hn[si] = (1.f - z) * n + z * ho;
        }
        asm volatile("bar.sync %0, 128;" :: "r"(barid) : "memory");
#pragma unroll
        for (int si = 0; si < SPT; si++) {
            int s = sbase + si;
            hsm[s * 132 + h_] = hn[si];
            int gs = seq0 + s;
            if (gs < nTot && t == flen[s] - 1)
                outp[(size_t)gs * Hh + h_] = hn[si];
        }
        asm volatile("bar.sync %0, 128;" :: "r"(barid) : "memory");
    }
}

// -------- episode attention scan: one block per batch row --------
__global__ __launch_bounds__(384, 1)
void scan_kernel(const float* __restrict__ at_bhh)
{
    extern __shared__ float sm[];
    float* Wsm = sm;              // 49152
    float* ghs = sm + 49152;      // 384
    float* hv  = ghs + 384;       // 128
    float* bs  = hv + 128;        // 384
    int b = blockIdx.x, tid = threadIdx.x;
    for (int i = tid * 4; i < 128 * G3; i += 1536)
        *(float4*)&Wsm[i] = *(const float4*)&g_WtT_at[i];
    bs[tid] = at_bhh[tid];
    if (tid < 128) hv[tid] = 0.f;
    __syncthreads();
    for (int t = 0; t < TC; t++) {
        float a0 = 0.f, a1 = 0.f;
#pragma unroll 8
        for (int k0 = 0; k0 < 128; k0 += 4) {
            float4 h4 = *(float4*)&hv[k0];
            a0 += h4.x * Wsm[(k0+0)*G3 + tid];
            a1 += h4.y * Wsm[(k0+1)*G3 + tid];
            a0 += h4.z * Wsm[(k0+2)*G3 + tid];
            a1 += h4.w * Wsm[(k0+3)*G3 + tid];
        }
        ghs[tid] = a0 + a1 + bs[tid];
        __syncthreads();
        if (tid < 128) {
            int seq = b * TC + t;
            const float* gi = g_GIat + (size_t)seq * G3;
            float r = sigmoidf(gi[tid] + ghs[tid]);
            float z = sigmoidf(gi[128 + tid] + ghs[128 + tid]);
            float n = tanhf(gi[256 + tid] + r * ghs[256 + tid]);
            float ho = hv[tid];
            float h2 = (1.f - z) * n + z * ho;
            float g = g_G[seq];
            hv[tid] = g * h2 + (1.f - g) * ho;
        }
        __syncthreads();
    }
    if (tid < 128) g_ebuf[b * Hh + tid] = hv[tid];
}

// -------- answer decode: one block per batch row --------
__global__ __launch_bounds__(384, 1)
void decode_kernel(const float* __restrict__ an_bhh, int nd)
{
    extern __shared__ float sm[];
    float* Wsm = sm;
    float* ghs = sm + 49152;
    float* hv  = ghs + 384;
    float* bs  = hv + 128;
    int b = blockIdx.x, tid = threadIdx.x;
    for (int i = tid * 4; i < 128 * G3; i += 1536)
        *(float4*)&Wsm[i] = *(const float4*)&g_WtT_an[i];
    bs[tid] = an_bhh[tid];
    if (tid < 128) hv[tid] = g_mem[b * Hh + tid];
    __syncthreads();
    const float* gi = g_GIan + b * G3;   // constant across steps
    for (int t = 0; t < nd; t++) {
        float a0 = 0.f, a1 = 0.f;
#pragma unroll 8
        for (int k0 = 0; k0 < 128; k0 += 4) {
            float4 h4 = *(float4*)&hv[k0];
            a0 += h4.x * Wsm[(k0+0)*G3 + tid];
            a1 += h4.y * Wsm[(k0+1)*G3 + tid];
            a0 += h4.z * Wsm[(k0+2)*G3 + tid];
            a1 += h4.w * Wsm[(k0+3)*G3 + tid];
        }
        ghs[tid] = a0 + a1 + bs[tid];
        __syncthreads();
        if (tid < 128) {
            float r = sigmoidf(gi[tid] + ghs[tid]);
            float z = sigmoidf(gi[128 + tid] + ghs[128 + tid]);
            float n = tanhf(gi[256 + tid] + r * ghs[256 + tid]);
            float h2 = (1.f - z) * n + z * hv[tid];
            hv[tid] = h2;
            g_Hdec[((size_t)b * nd + t) * Hh + tid] = h2;
        }
        __syncthreads();
    }
}

// -------- per-row log-softmax, row staged in smem, 512 threads --------
__global__ __launch_bounds__(512, 1)
void lsm_kernel(float* __restrict__ out)
{
    extern __shared__ float row[];       // Vv floats
    __shared__ float red[512];
    size_t base = (size_t)blockIdx.x * Vv;
    int tid = threadIdx.x;
    float mx = -1e30f;
    for (int i = tid * 4; i < Vv; i += 2048) {
        float4 v = *(float4*)&out[base + i];
        *(float4*)&row[i] = v;
        mx = fmaxf(mx, fmaxf(fmaxf(v.x, v.y), fmaxf(v.z, v.w)));
    }
    red[tid] = mx; __syncthreads();
    for (int o = 256; o; o >>= 1) { if (tid < o) red[tid] = fmaxf(red[tid], red[tid + o]); __syncthreads(); }
    mx = red[0];
    __syncthreads();
    float s = 0.f;
    for (int i = tid; i < Vv; i += 512) s += expf(row[i] - mx);
    red[tid] = s; __syncthreads();
    for (int o = 256; o; o >>= 1) { if (tid < o) red[tid] += red[tid + o]; __syncthreads(); }
    float lse = mx + logf(red[0]);
    for (int i = tid * 4; i < Vv; i += 2048) {
        float4 v = *(float4*)&row[i];
        v.x -= lse; v.y -= lse; v.z -= lse; v.w -= lse;
        *(float4*)&out[base + i] = v;
    }
}

// ---------------- host ----------------
static void* symaddr(const void* s) { void* p = nullptr; cudaGetSymbolAddress(&p, s); return p; }

extern "C" void kernel_launch(void* const* d_in, const int* in_sizes, int n_in,
                              void* d_out, int out_size)
{
    const int*   facts  = (const int*)d_in[0];
    const int*   fmask  = (const int*)d_in[1];
    const int*   quest  = (const int*)d_in[2];
    const int*   qmask  = (const int*)d_in[3];
    const float* embed  = (const float*)d_in[5];
    const float* ig_Wih = (const float*)d_in[6],  *ig_Whh = (const float*)d_in[7];
    const float* ig_bih = (const float*)d_in[8],  *ig_bhh = (const float*)d_in[9];
    const float* qg_Wih = (const float*)d_in[10], *qg_Whh = (const float*)d_in[11];
    const float* qg_bih = (const float*)d_in[12], *qg_bhh = (const float*)d_in[13];
    const float* at_Wih = (const float*)d_in[14], *at_Whh = (const float*)d_in[15];
    const float* at_bih = (const float*)d_in[16], *at_bhh = (const float*)d_in[17];
    const float* me_Wih = (const float*)d_in[18], *me_Whh = (const float*)d_in[19];
    const float* me_bih = (const float*)d_in[20], *me_bhh = (const float*)d_in[21];
    const float* an_Wih = (const float*)d_in[22], *an_Whh = (const float*)d_in[23];
    const float* an_bih = (const float*)d_in[24], *an_bhh = (const float*)d_in[25];
    const float* gate_W1 = (const float*)d_in[26], *gate_b1 = (const float*)d_in[27];
    const float* gate_W2 = (const float*)d_in[28], *gate_b2 = (const float*)d_in[29];
    const float* fc_W   = (const float*)d_in[30], *fc_b   = (const float*)d_in[31];
    float* out = (float*)d_out;
    (void)in_sizes; (void)n_in;

    int nd = out_size / (Bb * Vv);
    if (nd < 1) nd = 1; if (nd > 16) nd = 16;

    float* Etab   = (float*)symaddr(g_Etab);
    float* WtTig  = (float*)symaddr(g_WtT_ig);
    float* WtTqg  = (float*)symaddr(g_WtT_qg);
    float* WtTat  = (float*)symaddr(g_WtT_at);
    float* WtTan  = (float*)symaddr(g_WtT_an);
    float* WtTmi  = (float*)symaddr(g_WtT_meWih);
    float* WtTmh  = (float*)symaddr(g_WtT_meWhh);
    float* qemb   = (float*)symaddr(g_qemb);
    float* QGI    = (float*)symaddr(g_QGI);
    float* encf   = (float*)symaddr(g_encf);
    float* Z      = (float*)symaddr(g_Z);
    float* Tanhb  = (float*)symaddr(g_Tanh);
    float* GIat   = (float*)symaddr(g_GIat);
    float* yqb    = (float*)symaddr(g_yq);
    float* GIan   = (float*)symaddr(g_GIan);
    float* Hdec   = (float*)symaddr(g_Hdec);

    const int RECUR_SMEM = (49152 + SPB * 132 + 384) * 4 + SPB * 4;  // 223680
    const int SCAN_SMEM  = (49152 + 384 + 128 + 384) * 4;            // 200192
    const int LSM_SMEM   = Vv * 4;                                   // 200000
    cudaFuncSetAttribute(recur_kernel,  cudaFuncAttributeMaxDynamicSharedMemorySize, RECUR_SMEM);
    cudaFuncSetAttribute(scan_kernel,   cudaFuncAttributeMaxDynamicSharedMemorySize, SCAN_SMEM);
    cudaFuncSetAttribute(decode_kernel, cudaFuncAttributeMaxDynamicSharedMemorySize, SCAN_SMEM);
    cudaFuncSetAttribute(lsm_kernel,    cudaFuncAttributeMaxDynamicSharedMemorySize, LSM_SMEM);

    // 1. pre-transpose all recurrent weights to k-major (one launch)
    transpose6_kernel<<<6 * 192, 256>>>(ig_Whh, qg_Whh, at_Whh, an_Whh, me_Wih, me_Whh,
                                        WtTig, WtTqg, WtTat, WtTan, WtTmi, WtTmh);

    // 2. Etab = embed @ ig_Wih^T + ig_bih  (vocab-level input projection)
    { dim3 g(6, (Vv + 63) / 64); gemm_kernel<<<g, 256>>>(embed, ig_Wih, ig_bih, Etab, Vv, G3, Hh, 0); }

    // 3. question input projections
    qemb_kernel<<<(Bb * TI * Hh + 255) / 256, 256>>>(quest, embed);
    { dim3 g(6, (Bb * TI + 63) / 64); gemm_kernel<<<g, 256>>>(qemb, qg_Wih, qg_bih, QGI, Bb * TI, G3, Hh, 0); }

    // 4. fused fact + question recurrence (single wave: 134 + 3 = 137 blocks)
    const int FACT_BLOCKS = (Bb * TC + SPB - 1) / SPB;     // 134
    const int Q_BLOCKS    = (Bb + SPB - 1) / SPB;          // 3
    recur_kernel<<<FACT_BLOCKS + Q_BLOCKS, 512, RECUR_SMEM>>>(
        facts, fmask, qmask, ig_bhh, qg_bhh, FACT_BLOCKS);

    // 5. episodes
    initmem_kernel<<<(Bb * Hh + 255) / 256, 256>>>();
    { dim3 g(6, (Bb * TC + 63) / 64); gemm_kernel<<<g, 256>>>(encf, at_Wih, at_bih, GIat, Bb * TC, G3, Hh, 0); }
    for (int ep = 0; ep < EPIS; ep++) {
        zbuild_kernel<<<(Bb * TC * 512 + 255) / 256, 256>>>();
        { dim3 g(2, (Bb * TC + 63) / 64); gemm_kernel<<<g, 256>>>(Z, gate_W1, gate_b1, Tanhb, Bb * TC, Hh, 512, 1); }
        gatered_kernel<<<(Bb * TC + 7) / 8, 256>>>(gate_W2, gate_b2);
        scan_kernel<<<Bb, 384, SCAN_SMEM>>>(at_bhh);
        memstep_kernel<<<Bb, 384>>>(me_bih, me_bhh);
    }

    // 6. decode
    yq_kernel<<<(Bb * 256 + 255) / 256, 256>>>(embed);
    { dim3 g(6, 2); gemm_kernel<<<g, 256>>>(yqb, an_Wih, an_bih, GIan, Bb, G3, 256, 0); }
    decode_kernel<<<Bb, 384, SCAN_SMEM>>>(an_bhh, nd);

    // 7. logits GEMM straight into d_out, then in-place log-softmax
    { dim3 g((Vv + 63) / 64, (Bb * nd + 63) / 64);
      gemm_kernel<<<g, 256>>>(Hdec, fc_W, fc_b, out, Bb * nd, Vv, Hh, 0); }
    lsm_kernel<<<Bb * nd, 512, LSM_SMEM>>>(out);
}

// round 16
// speedup vs baseline: 1.5168x; 1.1766x over previous
#include <cuda_runtime.h>
#include <cuda_bf16.h>
#include <math.h>
#include <stdint.h>

#define Hh   128
#define Vv   50000
#define Bb   128
#define TC   50
#define TI   32
#define G3   384
#define EPIS 3
#define SPB  48     // seqs per recur block
#define SPT  12     // seqs per thread group member

// ---------------- device scratch ----------------
__device__ float g_Etab[(size_t)Vv * G3];
__device__ float g_WtT_ig[128 * G3];
__device__ float g_WtT_qg[128 * G3];
__device__ float g_WtT_at[128 * G3];
__device__ float g_WtT_an[128 * G3];
__device__ float g_WtT_meWih[128 * G3];
__device__ float g_WtT_meWhh[128 * G3];
__device__ float g_qemb[Bb * TI * Hh];
__device__ float g_QGI [Bb * TI * G3];
__device__ float g_encf[Bb * TC * Hh];
__device__ float g_q   [Bb * Hh];
__device__ float g_mem [Bb * Hh];
__device__ float g_Z   [Bb * TC * 512];
__device__ float g_Tanh[Bb * TC * Hh];
__device__ float g_G   [Bb * TC];
__device__ float g_GIat[Bb * TC * G3];
__device__ float g_ebuf[Bb * Hh];
__device__ float g_yq  [Bb * 256];
__device__ float g_GIan[Bb * G3];
__device__ __nv_bfloat16 g_embB [(size_t)Vv * Hh];
__device__ __nv_bfloat16 g_igWihB[G3 * Hh];
__device__ __nv_bfloat16 g_fcWb [(size_t)Vv * Hh];
__device__ __nv_bfloat16 g_Hdecb[16 * Bb * Hh];

__device__ __forceinline__ float sigmoidf(float x) { return 1.f / (1.f + expf(-x)); }

// ---------------- fp32 -> bf16 conversion ----------------
__global__ void f2b_kernel(const float* __restrict__ src, __nv_bfloat16* __restrict__ dst, int n) {
    int i = blockIdx.x * 256 + threadIdx.x;
    if (i < n) dst[i] = __float2bfloat16(src[i]);
}

// six Whh-style (384x128) -> k-major (128x384) transposes in one launch
__global__ void transpose6_kernel(const float* __restrict__ s0, const float* __restrict__ s1,
                                  const float* __restrict__ s2, const float* __restrict__ s3,
                                  const float* __restrict__ s4, const float* __restrict__ s5,
                                  float* __restrict__ d0, float* __restrict__ d1,
                                  float* __restrict__ d2, float* __restrict__ d3,
                                  float* __restrict__ d4, float* __restrict__ d5)
{
    int region = blockIdx.x / 192;
    int idx = (blockIdx.x % 192) * 256 + threadIdx.x;
    if (idx >= G3 * 128) return;
    const float* src; float* dst;
    switch (region) {
        case 0: src = s0; dst = d0; break;
        case 1: src = s1; dst = d1; break;
        case 2: src = s2; dst = d2; break;
        case 3: src = s3; dst = d3; break;
        case 4: src = s4; dst = d4; break;
        default: src = s5; dst = d5; break;
    }
    int j = idx >> 7, k = idx & 127;
    dst[k * G3 + j] = src[idx];
}

// ---------------- bf16 tensor-core GEMM, K=128 fixed ----------------
// C[MxN] (fp32) = A[Mx128]_bf16 @ B[Nx128]_bf16^T + bias[N]
// block: 256 thr = 8 warps; BM=128 (16 rows/warp), BN=64 shared via smem.
__global__ __launch_bounds__(256)
void mma_gemm128(const __nv_bfloat16* __restrict__ A, const __nv_bfloat16* __restrict__ Bw,
                 const float* __restrict__ bias, float* __restrict__ C, int M, int N)
{
    __shared__ __nv_bfloat16 Bs[64][136];
    int tid = threadIdx.x;
    int warp = tid >> 5, lane = tid & 31;
    int g = lane >> 2, t = lane & 3;
    int bm = blockIdx.y * 128, bn = blockIdx.x * 64;

    // cooperative B tile load (64 x 128 bf16), clamped rows
    for (int i = tid; i < 64 * 16; i += 256) {
        int r = i >> 4, c = (i & 15) << 3;
        int gn = bn + r; if (gn > N - 1) gn = N - 1;
        *(uint4*)&Bs[r][c] = *(const uint4*)&Bw[(size_t)gn * 128 + c];
    }

    // A fragments for all 8 k-steps, directly from global (L1/L2-hot)
    int rowa = bm + warp * 16 + g;
    int rowb = rowa + 8;
    int ra = rowa > M - 1 ? M - 1 : rowa;
    int rb = rowb > M - 1 ? M - 1 : rowb;
    const uint32_t* A0 = (const uint32_t*)(A + (size_t)ra * 128);
    const uint32_t* A1 = (const uint32_t*)(A + (size_t)rb * 128);
    uint32_t af[8][4];
#pragma unroll
    for (int ks = 0; ks < 8; ks++) {
        af[ks][0] = A0[ks * 8 + t];
        af[ks][1] = A1[ks * 8 + t];
        af[ks][2] = A0[ks * 8 + 4 + t];
        af[ks][3] = A1[ks * 8 + 4 + t];
    }
    __syncthreads();

    float acc[8][4] = {};
#pragma unroll
    for (int ks = 0; ks < 8; ks++) {
#pragma unroll
        for (int nt = 0; nt < 8; nt++) {
            uint32_t b0 = *(const uint32_t*)&Bs[nt * 8 + g][ks * 16 + 2 * t];
            uint32_t b1 = *(const uint32_t*)&Bs[nt * 8 + g][ks * 16 + 2 * t + 8];
            asm volatile(
                "mma.sync.aligned.m16n8k16.row.col.f32.bf16.bf16.f32 "
                "{%0,%1,%2,%3}, {%4,%5,%6,%7}, {%8,%9}, {%0,%1,%2,%3};\n"
                : "+f"(acc[nt][0]), "+f"(acc[nt][1]), "+f"(acc[nt][2]), "+f"(acc[nt][3])
                : "r"(af[ks][0]), "r"(af[ks][1]), "r"(af[ks][2]), "r"(af[ks][3]),
                  "r"(b0), "r"(b1));
        }
    }

#pragma unroll
    for (int nt = 0; nt < 8; nt++) {
        int c0 = bn + nt * 8 + 2 * t;
        if (c0 < N) {
            float bz = bias[c0];
            if (rowa < M) C[(size_t)rowa * N + c0] = acc[nt][0] + bz;
            if (rowb < M) C[(size_t)rowb * N + c0] = acc[nt][2] + bz;
        }
        int c1 = c0 + 1;
        if (c1 < N) {
            float bz = bias[c1];
            if (rowa < M) C[(size_t)rowa * N + c1] = acc[nt][1] + bz;
            if (rowb < M) C[(size_t)rowb * N + c1] = acc[nt][3] + bz;
        }
    }
}

// ---------------- fp32 GEMM (small shapes): C = act(A @ B^T + bias) ----------------
__global__ __launch_bounds__(256)
void gemm_kernel(const float* __restrict__ A, const float* __restrict__ Bm,
                 const float* __restrict__ bias, float* __restrict__ C,
                 int M, int N, int K, int act)
{
    __shared__ float As[32][68];
    __shared__ float Bs[32][68];
    int tid = threadIdx.x;
    int tx = tid & 15, ty = tid >> 4;
    int bm = blockIdx.y * 64, bn = blockIdx.x * 64;
    float acc[4][4] = {};
    for (int k0 = 0; k0 < K; k0 += 32) {
#pragma unroll
        for (int r = 0; r < 2; r++) {
            int li = tid + r * 256;
            int lm = li >> 3;
            int lk = (li & 7) << 2;
            int gm = bm + lm; if (gm > M - 1) gm = M - 1;
            float4 va = *(const float4*)&A[(size_t)gm * K + k0 + lk];
            As[lk][lm] = va.x; As[lk+1][lm] = va.y; As[lk+2][lm] = va.z; As[lk+3][lm] = va.w;
            int gn = bn + lm; if (gn > N - 1) gn = N - 1;
            float4 vb = *(const float4*)&Bm[(size_t)gn * K + k0 + lk];
            Bs[lk][lm] = vb.x; Bs[lk+1][lm] = vb.y; Bs[lk+2][lm] = vb.z; Bs[lk+3][lm] = vb.w;
        }
        __syncthreads();
#pragma unroll
        for (int k = 0; k < 32; k++) {
            float4 a  = *(float4*)&As[k][ty << 2];
            float4 bv = *(float4*)&Bs[k][tx << 2];
            acc[0][0]+=a.x*bv.x; acc[0][1]+=a.x*bv.y; acc[0][2]+=a.x*bv.z; acc[0][3]+=a.x*bv.w;
            acc[1][0]+=a.y*bv.x; acc[1][1]+=a.y*bv.y; acc[1][2]+=a.y*bv.z; acc[1][3]+=a.y*bv.w;
            acc[2][0]+=a.z*bv.x; acc[2][1]+=a.z*bv.y; acc[2][2]+=a.z*bv.z; acc[2][3]+=a.z*bv.w;
            acc[3][0]+=a.w*bv.x; acc[3][1]+=a.w*bv.y; acc[3][2]+=a.w*bv.z; acc[3][3]+=a.w*bv.w;
        }
        __syncthreads();
    }
#pragma unroll
    for (int i = 0; i < 4; i++) {
        int m = bm + (ty << 2) + i;
        if (m < M) {
#pragma unroll
            for (int j = 0; j < 4; j++) {
                int n = bn + (tx << 2) + j;
                if (n < N) {
                    float v = acc[i][j] + bias[n];
                    if (act) v = tanhf(v);
                    C[(size_t)m * N + n] = v;
                }
            }
        }
    }
}

__global__ void qemb_kernel(const int* __restrict__ quest, const float* __restrict__ embed) {
    int idx = blockIdx.x * 256 + threadIdx.x;
    if (idx < Bb * TI * Hh) {
        int i = idx >> 7, h = idx & 127;
        g_qemb[idx] = embed[(size_t)quest[i] * Hh + h];
    }
}

__global__ void initmem_kernel() {
    int i = blockIdx.x * 256 + threadIdx.x;
    if (i < Bb * Hh) g_mem[i] = g_q[i];
}

__global__ void yq_kernel(const float* __restrict__ embed) {
    int idx = blockIdx.x * 256 + threadIdx.x;
    if (idx < Bb * 256) {
        int b = idx >> 8, c = idx & 255;
        g_yq[idx] = (c < 128) ? embed[2 * Hh + c] : g_q[b * Hh + (c - 128)];
    }
}

__global__ void zbuild_kernel() {
    int idx = blockIdx.x * 256 + threadIdx.x;
    if (idx >= Bb * TC * 512) return;
    int seq = idx >> 9, c = idx & 511;
    int part = c >> 7, h = c & 127;
    int b = seq / TC;
    float f = g_encf[seq * Hh + h];
    float v;
    if      (part == 0) v = f * g_q[b * Hh + h];
    else if (part == 1) v = f * g_mem[b * Hh + h];
    else if (part == 2) v = fabsf(f - g_q[b * Hh + h]);
    else                v = fabsf(f - g_mem[b * Hh + h]);
    g_Z[idx] = v;
}

__global__ void gatered_kernel(const float* __restrict__ W2, const float* __restrict__ b2p) {
    int warp = threadIdx.x >> 5, lane = threadIdx.x & 31;
    int row = blockIdx.x * 8 + warp;
    if (row >= Bb * TC) return;
    float s = 0.f;
    for (int k = lane; k < Hh; k += 32) s += g_Tanh[row * Hh + k] * W2[k];
#pragma unroll
    for (int o = 16; o; o >>= 1) s += __shfl_xor_sync(0xffffffff, s, o);
    if (lane == 0) g_G[row] = sigmoidf(s + b2p[0]);
}

// memory = gru_cell(ebuf, memory, me_*) -- one block per batch row, 384 threads
__global__ void memstep_kernel(const float* __restrict__ bih, const float* __restrict__ bhh)
{
    __shared__ float xs[128], hs[128], gis[384], ghs[384];
    int b = blockIdx.x, tid = threadIdx.x;
    if (tid < 128) { xs[tid] = g_ebuf[b * Hh + tid]; hs[tid] = g_mem[b * Hh + tid]; }
    __syncthreads();
    float ai = bih[tid], ah = bhh[tid];
#pragma unroll 8
    for (int k = 0; k < 128; k++) {
        ai += xs[k] * __ldg(&g_WtT_meWih[k * G3 + tid]);
        ah += hs[k] * __ldg(&g_WtT_meWhh[k * G3 + tid]);
    }
    gis[tid] = ai; ghs[tid] = ah;
    __syncthreads();
    if (tid < 128) {
        float r = sigmoidf(gis[tid] + ghs[tid]);
        float z = sigmoidf(gis[128 + tid] + ghs[128 + tid]);
        float n = tanhf(gis[256 + tid] + r * ghs[256 + tid]);
        g_mem[b * Hh + tid] = (1.f - z) * n + z * hs[tid];
    }
}

// -------- fused fact + question GRU recurrence: 48 seqs/block, 512 threads --------
__global__ __launch_bounds__(512, 1)
void recur_kernel(const int* __restrict__ facts, const int* __restrict__ fmasks,
                  const int* __restrict__ qmasks,
                  const float* __restrict__ igbhh, const float* __restrict__ qgbhh,
                  int factBlocks)
{
    extern __shared__ float sm[];
    float* Wsm = sm;
    float* hsm = sm + 49152;
    float* bsm = hsm + SPB * 132;
    int*   flen = (int*)(bsm + 384);

    bool isQ = (blockIdx.x >= factBlocks);
    int  seq0 = (isQ ? (blockIdx.x - factBlocks) : blockIdx.x) * SPB;
    int  nTot = isQ ? Bb : Bb * TC;
    const float* WT   = isQ ? g_WtT_qg : g_WtT_ig;
    const float* bhh  = isQ ? qgbhh : igbhh;
    const int*  masks = isQ ? qmasks : fmasks;
    float*      outp  = isQ ? g_q : g_encf;

    int tid = threadIdx.x;
    for (int i = tid * 4; i < 128 * G3; i += 2048)
        *(float4*)&Wsm[i] = *(const float4*)&WT[i];
    if (tid < 384) bsm[tid] = bhh[tid];
    if (tid < SPB) {
        int gs = seq0 + tid; if (gs > nTot - 1) gs = nTot - 1;
        int c = 0;
        for (int t = 0; t < TI; t++) c += (masks[gs * TI + t] == 0) ? 1 : 0;
        flen[tid] = (c > 0) ? c : 1;
    }
    for (int i = tid; i < SPB * 132; i += 512) hsm[i] = 0.f;
    __syncthreads();

    int h_ = tid & 127;
    int grp = tid >> 7;
    int sbase = grp * SPT;
    int barid = grp + 1;
    float br = bsm[h_], bz = bsm[128 + h_], bn_ = bsm[256 + h_];

    for (int t = 0; t < TI; t++) {
        float gr[SPT], gz[SPT], gn[SPT];
#pragma unroll
        for (int si = 0; si < SPT; si++) {
            int gs = seq0 + sbase + si; if (gs > nTot - 1) gs = nTot - 1;
            const float* gi = isQ ? (g_QGI + ((size_t)gs * TI + t) * G3)
                                  : (g_Etab + (size_t)__ldg(&facts[gs * TI + t]) * G3);
            gr[si] = __ldg(&gi[h_]);
            gz[si] = __ldg(&gi[128 + h_]);
            gn[si] = __ldg(&gi[256 + h_]);
        }
        float ar[SPT] = {}, az[SPT] = {}, aw[SPT] = {};
#pragma unroll 2
        for (int k0 = 0; k0 < 128; k0 += 4) {
            float wr0 = Wsm[(k0+0)*G3 + h_],       wr1 = Wsm[(k0+1)*G3 + h_];
            float wr2 = Wsm[(k0+2)*G3 + h_],       wr3 = Wsm[(k0+3)*G3 + h_];
            float wz0 = Wsm[(k0+0)*G3 + 128 + h_], wz1 = Wsm[(k0+1)*G3 + 128 + h_];
            float wz2 = Wsm[(k0+2)*G3 + 128 + h_], wz3 = Wsm[(k0+3)*G3 + 128 + h_];
            float wn0 = Wsm[(k0+0)*G3 + 256 + h_], wn1 = Wsm[(k0+1)*G3 + 256 + h_];
            float wn2 = Wsm[(k0+2)*G3 + 256 + h_], wn3 = Wsm[(k0+3)*G3 + 256 + h_];
#pragma unroll
            for (int si = 0; si < SPT; si++) {
                float4 h4 = *(float4*)&hsm[(sbase + si) * 132 + k0];
                ar[si] += wr0*h4.x + wr1*h4.y + wr2*h4.z + wr3*h4.w;
                az[si] += wz0*h4.x + wz1*h4.y + wz2*h4.z + wz3*h4.w;
                aw[si] += wn0*h4.x + wn1*h4.y + wn2*h4.z + wn3*h4.w;
            }
        }
        float hn[SPT];
#pragma unroll
        for (int si = 0; si < SPT; si++) {
            float ho = hsm[(sbase + si) * 132 + h_];
            float r = sigmoidf(gr[si] + ar[si] + br);
            float z = sigmoidf(gz[si] + az[si] + bz);
            float n = tanhf(gn[si] + r * (aw[si] + bn_));
            hn[si] = (1.f - z) * n + z * ho;
        }
        asm volatile("bar.sync %0, 128;" :: "r"(barid) : "memory");
#pragma unroll
        for (int si = 0; si < SPT; si++) {
            int s = sbase + si;
            hsm[s * 132 + h_] = hn[si];
            int gs = seq0 + s;
            if (gs < nTot && t == flen[s] - 1)
                outp[(size_t)gs * Hh + h_] = hn[si];
        }
        asm volatile("bar.sync %0, 128;" :: "r"(barid) : "memory");
    }
}

// -------- episode attention scan: one block per batch row --------
__global__ __launch_bounds__(384, 1)
void scan_kernel(const float* __restrict__ at_bhh)
{
    extern __shared__ float sm[];
    float* Wsm = sm;
    float* ghs = sm + 49152;
    float* hv  = ghs + 384;
    float* bs  = hv + 128;
    int b = blockIdx.x, tid = threadIdx.x;
    for (int i = tid * 4; i < 128 * G3; i += 1536)
        *(float4*)&Wsm[i] = *(const float4*)&g_WtT_at[i];
    bs[tid] = at_bhh[tid];
    if (tid < 128) hv[tid] = 0.f;
    __syncthreads();
    for (int t = 0; t < TC; t++) {
        float a0 = 0.f, a1 = 0.f;
#pragma unroll 8
        for (int k0 = 0; k0 < 128; k0 += 4) {
            float4 h4 = *(float4*)&hv[k0];
            a0 += h4.x * Wsm[(k0+0)*G3 + tid];
            a1 += h4.y * Wsm[(k0+1)*G3 + tid];
            a0 += h4.z * Wsm[(k0+2)*G3 + tid];
            a1 += h4.w * Wsm[(k0+3)*G3 + tid];
        }
        ghs[tid] = a0 + a1 + bs[tid];
        __syncthreads();
        if (tid < 128) {
            int seq = b * TC + t;
            const float* gi = g_GIat + (size_t)seq * G3;
            float r = sigmoidf(gi[tid] + ghs[tid]);
            float z = sigmoidf(gi[128 + tid] + ghs[128 + tid]);
            float n = tanhf(gi[256 + tid] + r * ghs[256 + tid]);
            float ho = hv[tid];
            float h2 = (1.f - z) * n + z * ho;
            float g = g_G[seq];
            hv[tid] = g * h2 + (1.f - g) * ho;
        }
        __syncthreads();
    }
    if (tid < 128) g_ebuf[b * Hh + tid] = hv[tid];
}

// -------- answer decode: one block per batch row; hiddens stored bf16 --------
__global__ __launch_bounds__(384, 1)
void decode_kernel(const float* __restrict__ an_bhh, int nd)
{
    extern __shared__ float sm[];
    float* Wsm = sm;
    float* ghs = sm + 49152;
    float* hv  = ghs + 384;
    float* bs  = hv + 128;
    int b = blockIdx.x, tid = threadIdx.x;
    for (int i = tid * 4; i < 128 * G3; i += 1536)
        *(float4*)&Wsm[i] = *(const float4*)&g_WtT_an[i];
    bs[tid] = an_bhh[tid];
    if (tid < 128) hv[tid] = g_mem[b * Hh + tid];
    __syncthreads();
    const float* gi = g_GIan + b * G3;
    for (int t = 0; t < nd; t++) {
        float a0 = 0.f, a1 = 0.f;
#pragma unroll 8
        for (int k0 = 0; k0 < 128; k0 += 4) {
            float4 h4 = *(float4*)&hv[k0];
            a0 += h4.x * Wsm[(k0+0)*G3 + tid];
            a1 += h4.y * Wsm[(k0+1)*G3 + tid];
            a0 += h4.z * Wsm[(k0+2)*G3 + tid];
            a1 += h4.w * Wsm[(k0+3)*G3 + tid];
        }
        ghs[tid] = a0 + a1 + bs[tid];
        __syncthreads();
        if (tid < 128) {
            float r = sigmoidf(gi[tid] + ghs[tid]);
            float z = sigmoidf(gi[128 + tid] + ghs[128 + tid]);
            float n = tanhf(gi[256 + tid] + r * ghs[256 + tid]);
            float h2 = (1.f - z) * n + z * hv[tid];
            hv[tid] = h2;
            g_Hdecb[((size_t)b * nd + t) * Hh + tid] = __float2bfloat16(h2);
        }
        __syncthreads();
    }
}

// -------- per-row log-softmax, row staged in smem, 512 threads --------
__global__ __launch_bounds__(512, 1)
void lsm_kernel(float* __restrict__ out)
{
    extern __shared__ float row[];
    __shared__ float red[512];
    size_t base = (size_t)blockIdx.x * Vv;
    int tid = threadIdx.x;
    float mx = -1e30f;
    for (int i = tid * 4; i < Vv; i += 2048) {
        float4 v = *(float4*)&out[base + i];
        *(float4*)&row[i] = v;
        mx = fmaxf(mx, fmaxf(fmaxf(v.x, v.y), fmaxf(v.z, v.w)));
    }
    red[tid] = mx; __syncthreads();
    for (int o = 256; o; o >>= 1) { if (tid < o) red[tid] = fmaxf(red[tid], red[tid + o]); __syncthreads(); }
    mx = red[0];
    __syncthreads();
    float s = 0.f;
    for (int i = tid; i < Vv; i += 512) s += expf(row[i] - mx);
    red[tid] = s; __syncthreads();
    for (int o = 256; o; o >>= 1) { if (tid < o) red[tid] += red[tid + o]; __syncthreads(); }
    float lse = mx + logf(red[0]);
    for (int i = tid * 4; i < Vv; i += 2048) {
        float4 v = *(float4*)&row[i];
        v.x -= lse; v.y -= lse; v.z -= lse; v.w -= lse;
        *(float4*)&out[base + i] = v;
    }
}

// ---------------- host ----------------
static void* symaddr(const void* s) { void* p = nullptr; cudaGetSymbolAddress(&p, s); return p; }

extern "C" void kernel_launch(void* const* d_in, const int* in_sizes, int n_in,
                              void* d_out, int out_size)
{
    const int*   facts  = (const int*)d_in[0];
    const int*   fmask  = (const int*)d_in[1];
    const int*   quest  = (const int*)d_in[2];
    const int*   qmask  = (const int*)d_in[3];
    const float* embed  = (const float*)d_in[5];
    const float* ig_Wih = (const float*)d_in[6],  *ig_Whh = (const float*)d_in[7];
    const float* ig_bih = (const float*)d_in[8],  *ig_bhh = (const float*)d_in[9];
    const float* qg_Wih = (const float*)d_in[10], *qg_Whh = (const float*)d_in[11];
    const float* qg_bih = (const float*)d_in[12], *qg_bhh = (const float*)d_in[13];
    const float* at_Wih = (const float*)d_in[14], *at_Whh = (const float*)d_in[15];
    const float* at_bih = (const float*)d_in[16], *at_bhh = (const float*)d_in[17];
    const float* me_Wih = (const float*)d_in[18], *me_Whh = (const float*)d_in[19];
    const float* me_bih = (const float*)d_in[20], *me_bhh = (const float*)d_in[21];
    const float* an_Wih = (const float*)d_in[22], *an_Whh = (const float*)d_in[23];
    const float* an_bih = (const float*)d_in[24], *an_bhh = (const float*)d_in[25];
    const float* gate_W1 = (const float*)d_in[26], *gate_b1 = (const float*)d_in[27];
    const float* gate_W2 = (const float*)d_in[28], *gate_b2 = (const float*)d_in[29];
    const float* fc_W   = (const float*)d_in[30], *fc_b   = (const float*)d_in[31];
    float* out = (float*)d_out;
    (void)in_sizes; (void)n_in;

    int nd = out_size / (Bb * Vv);
    if (nd < 1) nd = 1; if (nd > 16) nd = 16;

    float* Etab   = (float*)symaddr(g_Etab);
    float* WtTig  = (float*)symaddr(g_WtT_ig);
    float* WtTqg  = (float*)symaddr(g_WtT_qg);
    float* WtTat  = (float*)symaddr(g_WtT_at);
    float* WtTan  = (float*)symaddr(g_WtT_an);
    float* WtTmi  = (float*)symaddr(g_WtT_meWih);
    float* WtTmh  = (float*)symaddr(g_WtT_meWhh);
    float* qemb   = (float*)symaddr(g_qemb);
    float* QGI    = (float*)symaddr(g_QGI);
    float* encf   = (float*)symaddr(g_encf);
    float* Z      = (float*)symaddr(g_Z);
    float* Tanhb  = (float*)symaddr(g_Tanh);
    float* GIat   = (float*)symaddr(g_GIat);
    float* yqb    = (float*)symaddr(g_yq);
    float* GIan   = (float*)symaddr(g_GIan);
    __nv_bfloat16* embB   = (__nv_bfloat16*)symaddr(g_embB);
    __nv_bfloat16* igWihB = (__nv_bfloat16*)symaddr(g_igWihB);
    __nv_bfloat16* fcWb   = (__nv_bfloat16*)symaddr(g_fcWb);
    __nv_bfloat16* Hdecb  = (__nv_bfloat16*)symaddr(g_Hdecb);

    const int RECUR_SMEM = (49152 + SPB * 132 + 384) * 4 + SPB * 4;
    const int SCAN_SMEM  = (49152 + 384 + 128 + 384) * 4;
    const int LSM_SMEM   = Vv * 4;
    cudaFuncSetAttribute(recur_kernel,  cudaFuncAttributeMaxDynamicSharedMemorySize, RECUR_SMEM);
    cudaFuncSetAttribute(scan_kernel,   cudaFuncAttributeMaxDynamicSharedMemorySize, SCAN_SMEM);
    cudaFuncSetAttribute(decode_kernel, cudaFuncAttributeMaxDynamicSharedMemorySize, SCAN_SMEM);
    cudaFuncSetAttribute(lsm_kernel,    cudaFuncAttributeMaxDynamicSharedMemorySize, LSM_SMEM);

    // 0. bf16 conversions
    f2b_kernel<<<(Vv * Hh + 255) / 256, 256>>>(embed, embB, Vv * Hh);
    f2b_kernel<<<(G3 * Hh + 255) / 256, 256>>>(ig_Wih, igWihB, G3 * Hh);
    f2b_kernel<<<(Vv * Hh + 255) / 256, 256>>>(fc_W, fcWb, Vv * Hh);

    // 1. pre-transpose all recurrent weights to k-major (one launch)
    transpose6_kernel<<<6 * 192, 256>>>(ig_Whh, qg_Whh, at_Whh, an_Whh, me_Wih, me_Whh,
                                        WtTig, WtTqg, WtTat, WtTan, WtTmi, WtTmh);

    // 2. Etab = embed @ ig_Wih^T + ig_bih  (bf16 tensor-core, fp32 accumulate)
    { dim3 g(G3 / 64, (Vv + 127) / 128);
      mma_gemm128<<<g, 256>>>(embB, igWihB, ig_bih, Etab, Vv, G3); }

    // 3. question input projections (fp32)
    qemb_kernel<<<(Bb * TI * Hh + 255) / 256, 256>>>(quest, embed);
    { dim3 g(6, (Bb * TI + 63) / 64); gemm_kernel<<<g, 256>>>(qemb, qg_Wih, qg_bih, QGI, Bb * TI, G3, Hh, 0); }

    // 4. fused fact + question recurrence (single wave)
    const int FACT_BLOCKS = (Bb * TC + SPB - 1) / SPB;
    const int Q_BLOCKS    = (Bb + SPB - 1) / SPB;
    recur_kernel<<<FACT_BLOCKS + Q_BLOCKS, 512, RECUR_SMEM>>>(
        facts, fmask, qmask, ig_bhh, qg_bhh, FACT_BLOCKS);

    // 5. episodes
    initmem_kernel<<<(Bb * Hh + 255) / 256, 256>>>();
    { dim3 g(6, (Bb * TC + 63) / 64); gemm_kernel<<<g, 256>>>(encf, at_Wih, at_bih, GIat, Bb * TC, G3, Hh, 0); }
    for (int ep = 0; ep < EPIS; ep++) {
        zbuild_kernel<<<(Bb * TC * 512 + 255) / 256, 256>>>();
        { dim3 g(2, (Bb * TC + 63) / 64); gemm_kernel<<<g, 256>>>(Z, gate_W1, gate_b1, Tanhb, Bb * TC, Hh, 512, 1); }
        gatered_kernel<<<(Bb * TC + 7) / 8, 256>>>(gate_W2, gate_b2);
        scan_kernel<<<Bb, 384, SCAN_SMEM>>>(at_bhh);
        memstep_kernel<<<Bb, 384>>>(me_bih, me_bhh);
    }

    // 6. decode
    yq_kernel<<<(Bb * 256 + 255) / 256, 256>>>(embed);
    { dim3 g(6, 2); gemm_kernel<<<g, 256>>>(yqb, an_Wih, an_bih, GIan, Bb, G3, 256, 0); }
    decode_kernel<<<Bb, 384, SCAN_SMEM>>>(an_bhh, nd);

    // 7. logits GEMM (bf16 tensor-core) straight into d_out, then in-place log-softmax
    { dim3 g((Vv + 63) / 64, (Bb * nd + 127) / 128);
      mma_gemm128<<<g, 256>>>(Hdecb, fcWb, fc_b, out, Bb * nd, Vv); }
    lsm_kernel<<<Bb * nd, 512, LSM_SMEM>>>(out);
}